// round 7
// baseline (speedup 1.0000x reference)
#include <cuda_runtime.h>
#include <cuda_fp16.h>
#include <mma.h>
#include <cstdint>

using namespace nvcuda;

// Problem constants
#define B_DIM    32
#define S_DIM    2048
#define H_DIM    4096
#define R_DIM    64
#define TILE_M   64
#define KC       32                    // K elements per chunk
#define NCHUNK   (H_DIM / KC)          // 128
#define NTHREADS 256

// SMEM (half): row stride 40 halves = 80 B (conflict-free, ldm multiple of 8)
#define LDH        40
#define X_STAGE_H  (TILE_M * LDH)                 // 2560 halves = 5120 B
#define W_STAGE_H  (R_DIM * LDH)                  // 2560 halves = 5120 B
#define STAGE_H    (X_STAGE_H + W_STAGE_H)        // 5120 halves
#define STAGE_B    (STAGE_H * 2)                  // 10240 B
#define SMEM_TOTAL (2 * STAGE_B)                  // 20480 B (x4 CTAs = 81920)

__device__ __forceinline__ uint32_t smem_u32(const void* p) {
    uint32_t r;
    asm("{ .reg .u64 t; cvta.to.shared.u64 t, %1; cvt.u32.u64 %0, t; }"
        : "=r"(r) : "l"(p));
    return r;
}

__device__ __forceinline__ void sts64(uint32_t addr, uint32_t a, uint32_t b) {
    asm volatile("st.shared.v2.b32 [%0], {%1, %2};"
                 :: "r"(addr), "r"(a), "r"(b));
}

__global__ void __launch_bounds__(NTHREADS, 4)
multilora_fp16_m64_kernel(const float* __restrict__ x,
                          const int* __restrict__ adapter_ids,
                          const float* __restrict__ weight,
                          float* __restrict__ out) {
    extern __shared__ __align__(16) __half smem[];
    const uint32_t smem_base = smem_u32(smem);

    const int tid = threadIdx.x;
    const int wid = tid >> 5;

    const int mtile = blockIdx.x;       // 0..31
    const int b     = blockIdx.y;       // 0..31
    const int m0    = mtile * TILE_M;
    const int aid   = __ldg(adapter_ids + b);

    // ---- producer mapping: 1024 float4 quads / chunk over 256 threads = 4 each
    // quads [0,512): x tile (64 rows); [512,1024): w tile (64 rows).
    const float* gptr[4];
    uint32_t sm_off[4];    // byte offset within a stage buffer
    #pragma unroll
    for (int j = 0; j < 4; j++) {
        int i = tid + j * NTHREADS;
        if (i < 512) {
            int row = i >> 3, q = i & 7;
            gptr[j]  = x + ((size_t)(b * S_DIM + m0 + row)) * H_DIM + q * 4;
            sm_off[j] = (uint32_t)((row * LDH + q * 4) * 2);
        } else {
            int t = i - 512;
            int row = t >> 3, q = t & 7;
            gptr[j]  = weight + ((size_t)(aid * R_DIM + row)) * H_DIM + q * 4;
            sm_off[j] = (uint32_t)((X_STAGE_H + row * LDH + q * 4) * 2);
        }
    }

    // ---- consumer mapping: 8 warps, 16x32 warp tiles (4 along M, 2 along N)
    const int wm = wid >> 1;            // 0..3 -> 16-row band
    const int wn = wid & 1;             // 0..1 -> 32-col band

    wmma::fragment<wmma::accumulator, 16, 16, 16, float> acc[2];
    wmma::fill_fragment(acc[0], 0.0f);
    wmma::fill_fragment(acc[1], 0.0f);

    // ---- single staging set (loads for kc+1 issued inside iter kc)
    float4 cur[4];
    #pragma unroll
    for (int j = 0; j < 4; j++)
        cur[j] = *(const float4*)(gptr[j]);

    for (int kc = 0; kc < NCHUNK; kc++) {
        const int s = kc & 1;
        const uint32_t sbase = smem_base + s * STAGE_B;
        __half* xs = smem + s * STAGE_H;
        __half* ws = xs + X_STAGE_H;

        // RN convert f32 -> half2 + STS.64 (consumes cur)
        #pragma unroll
        for (int j = 0; j < 4; j++) {
            __half2 h0 = __floats2half2_rn(cur[j].x, cur[j].y);
            __half2 h1 = __floats2half2_rn(cur[j].z, cur[j].w);
            sts64(sbase + sm_off[j],
                  *(const uint32_t*)&h0, *(const uint32_t*)&h1);
        }

        // issue loads for chunk kc+1 (gmem-only; legal before the barrier,
        // lands during barrier + WMMA below)
        if (kc + 1 < NCHUNK) {
            #pragma unroll
            for (int j = 0; j < 4; j++)
                cur[j] = *(const float4*)(gptr[j] + (size_t)(kc + 1) * KC);
        }

        // Single barrier per chunk:
        //  - RAW: STS(stage s) visible before WMMA(stage s)
        //  - WAR: WMMA(stage s) of iter kc-2 preceded the barrier of iter kc-1
        __syncthreads();

        // compute: 2 k-steps of m16n16k16 on a 16x32 warp tile
        #pragma unroll
        for (int kk = 0; kk < KC; kk += 16) {
            wmma::fragment<wmma::matrix_a, 16, 16, 16, __half,
                           wmma::row_major> af;
            wmma::fragment<wmma::matrix_b, 16, 16, 16, __half,
                           wmma::col_major> bf[2];
            wmma::load_matrix_sync(af, xs + (wm * 16) * LDH + kk, LDH);
            #pragma unroll
            for (int fj = 0; fj < 2; fj++)
                wmma::load_matrix_sync(bf[fj],
                    ws + (wn * 32 + fj * 16) * LDH + kk, LDH);
            #pragma unroll
            for (int fj = 0; fj < 2; fj++)
                wmma::mma_sync(acc[fj], af, bf[fj], acc[fj]);
        }
    }

    // ---- epilogue: direct store, out is [B, S, R] row-major
    float* obase = out + ((size_t)(b * S_DIM + m0 + wm * 16)) * R_DIM + wn * 32;
    #pragma unroll
    for (int fj = 0; fj < 2; fj++)
        wmma::store_matrix_sync(obase + fj * 16, acc[fj], R_DIM,
                                wmma::mem_row_major);
}

extern "C" void kernel_launch(void* const* d_in, const int* in_sizes, int n_in,
                              void* d_out, int out_size) {
    const float* x   = (const float*)d_in[0];
    const int*   ids = (const int*)d_in[1];
    const float* w   = (const float*)d_in[2];
    float* out = (float*)d_out;

    const int b = in_sizes[1];   // number of requests (32)

    cudaFuncSetAttribute(multilora_fp16_m64_kernel,
                         cudaFuncAttributeMaxDynamicSharedMemorySize, SMEM_TOTAL);

    dim3 grid(S_DIM / TILE_M, b);
    multilora_fp16_m64_kernel<<<grid, NTHREADS, SMEM_TOTAL>>>(x, ids, w, out);
}

// round 8
// speedup vs baseline: 1.5123x; 1.5123x over previous
#include <cuda_runtime.h>
#include <cuda_fp16.h>
#include <mma.h>
#include <cstdint>

using namespace nvcuda;

// Problem constants
#define B_DIM    32
#define S_DIM    2048
#define H_DIM    4096
#define R_DIM    64
#define TILE_M   128
#define KC       64                    // K elements per chunk (was 32)
#define NCHUNK   (H_DIM / KC)          // 64
#define NTHREADS 256

// SMEM (half): row stride 72 halves = 144 B.
//  - ldm multiple of 8 halves ✓
//  - 144*r mod 128 = 16r mod 128 distinct for r=0..7 -> conflict-free
#define LDH        72
#define X_STAGE_H  (TILE_M * LDH)                 // 9216 halves = 18432 B
#define W_STAGE_H  (R_DIM * LDH)                  // 4608 halves = 9216 B
#define STAGE_H    (X_STAGE_H + W_STAGE_H)        // 13824 halves
#define STAGE_B    (STAGE_H * 2)                  // 27648 B
#define SMEM_TOTAL (2 * STAGE_B)                  // 55296 B (x2 CTAs = 110592)

__device__ __forceinline__ uint32_t smem_u32(const void* p) {
    uint32_t r;
    asm("{ .reg .u64 t; cvta.to.shared.u64 t, %1; cvt.u32.u64 %0, t; }"
        : "=r"(r) : "l"(p));
    return r;
}

__device__ __forceinline__ void sts64(uint32_t addr, uint32_t a, uint32_t b) {
    asm volatile("st.shared.v2.b32 [%0], {%1, %2};"
                 :: "r"(addr), "r"(a), "r"(b));
}

__global__ void __launch_bounds__(NTHREADS, 2)
multilora_fp16_k64_kernel(const float* __restrict__ x,
                          const int* __restrict__ adapter_ids,
                          const float* __restrict__ weight,
                          float* __restrict__ out) {
    extern __shared__ __align__(16) __half smem[];
    const uint32_t smem_base = smem_u32(smem);

    const int tid = threadIdx.x;
    const int wid = tid >> 5;

    const int mtile = blockIdx.x;       // 0..15
    const int b     = blockIdx.y;       // 0..31
    const int m0    = mtile * TILE_M;
    const int aid   = __ldg(adapter_ids + b);

    // ---- producer mapping: 3072 float4 quads / chunk over 256 threads = 12 each
    // quads [0,2048): x tile (row = i/16, q = i%16); [2048,3072): w tile.
    const float* gptr[12];
    uint32_t sm_off[12];    // byte offset within a stage buffer
    #pragma unroll
    for (int j = 0; j < 12; j++) {
        int i = tid + j * NTHREADS;
        if (i < 2048) {
            int row = i >> 4, q = i & 15;
            gptr[j]  = x + ((size_t)(b * S_DIM + m0 + row)) * H_DIM + q * 4;
            sm_off[j] = (uint32_t)((row * LDH + q * 4) * 2);
        } else {
            int t = i - 2048;
            int row = t >> 4, q = t & 15;
            gptr[j]  = weight + ((size_t)(aid * R_DIM + row)) * H_DIM + q * 4;
            sm_off[j] = (uint32_t)((X_STAGE_H + row * LDH + q * 4) * 2);
        }
    }

    // ---- consumer mapping: 8 warps, 32x32 warp tiles (4 along M, 2 along N)
    const int wm = wid >> 1;
    const int wn = wid & 1;

    wmma::fragment<wmma::accumulator, 16, 16, 16, float> acc[2][2];
    #pragma unroll
    for (int fi = 0; fi < 2; fi++)
        #pragma unroll
        for (int fj = 0; fj < 2; fj++)
            wmma::fill_fragment(acc[fi][fj], 0.0f);

    // ---- single staging set; loads for chunk kc+1 issued inside iter kc
    float4 cur[12];
    #pragma unroll
    for (int j = 0; j < 12; j++)
        cur[j] = *(const float4*)(gptr[j]);

    for (int kc = 0; kc < NCHUNK; kc++) {
        const int s = kc & 1;
        const uint32_t sbase = smem_base + s * STAGE_B;
        __half* xs = smem + s * STAGE_H;
        __half* ws = xs + X_STAGE_H;

        // RN convert f32 -> half2 + STS.64 (consumes cur quickly)
        #pragma unroll
        for (int j = 0; j < 12; j++) {
            __half2 h0 = __floats2half2_rn(cur[j].x, cur[j].y);
            __half2 h1 = __floats2half2_rn(cur[j].z, cur[j].w);
            sts64(sbase + sm_off[j],
                  *(const uint32_t*)&h0, *(const uint32_t*)&h1);
        }

        // issue loads for chunk kc+1 (lands during barrier + 4 k-steps below)
        if (kc + 1 < NCHUNK) {
            #pragma unroll
            for (int j = 0; j < 12; j++)
                cur[j] = *(const float4*)(gptr[j] + (size_t)(kc + 1) * KC);
        }

        // Single barrier per chunk:
        //  - RAW: STS(stage s) visible before WMMA(stage s)
        //  - WAR: WMMA on stage s of iter kc-2 preceded iter kc-1's barrier
        __syncthreads();

        // compute: 4 k-steps of m16n16k16
        #pragma unroll
        for (int kk = 0; kk < KC; kk += 16) {
            wmma::fragment<wmma::matrix_a, 16, 16, 16, __half,
                           wmma::row_major> af[2];
            wmma::fragment<wmma::matrix_b, 16, 16, 16, __half,
                           wmma::col_major> bf[2];
            #pragma unroll
            for (int fi = 0; fi < 2; fi++)
                wmma::load_matrix_sync(af[fi],
                    xs + (wm * 32 + fi * 16) * LDH + kk, LDH);
            #pragma unroll
            for (int fj = 0; fj < 2; fj++)
                wmma::load_matrix_sync(bf[fj],
                    ws + (wn * 32 + fj * 16) * LDH + kk, LDH);
            #pragma unroll
            for (int fi = 0; fi < 2; fi++)
                #pragma unroll
                for (int fj = 0; fj < 2; fj++)
                    wmma::mma_sync(acc[fi][fj], af[fi], bf[fj], acc[fi][fj]);
        }
    }

    // ---- epilogue: direct store to gmem, out is [B, S, R] row-major
    float* obase = out + ((size_t)(b * S_DIM + m0 + wm * 32)) * R_DIM + wn * 32;
    #pragma unroll
    for (int fi = 0; fi < 2; fi++)
        #pragma unroll
        for (int fj = 0; fj < 2; fj++)
            wmma::store_matrix_sync(obase + (size_t)fi * 16 * R_DIM + fj * 16,
                                    acc[fi][fj], R_DIM, wmma::mem_row_major);
}

extern "C" void kernel_launch(void* const* d_in, const int* in_sizes, int n_in,
                              void* d_out, int out_size) {
    const float* x   = (const float*)d_in[0];
    const int*   ids = (const int*)d_in[1];
    const float* w   = (const float*)d_in[2];
    float* out = (float*)d_out;

    const int b = in_sizes[1];   // number of requests (32)

    cudaFuncSetAttribute(multilora_fp16_k64_kernel,
                         cudaFuncAttributeMaxDynamicSharedMemorySize, SMEM_TOTAL);

    dim3 grid(S_DIM / TILE_M, b);
    multilora_fp16_k64_kernel<<<grid, NTHREADS, SMEM_TOTAL>>>(x, ids, w, out);
}